// round 1
// baseline (speedup 1.0000x reference)
#include <cuda_runtime.h>
#include <cuda_bf16.h>
#include <math.h>

#define N_NODES 50000
#define N_EDGES 800000
#define D 128

// -------- scratch (no allocations allowed) --------
__device__ int   g_deg[N_NODES];
__device__ float g_dinv[N_NODES];
__device__ int   g_off[N_NODES + 1];
__device__ int   g_cursor[N_NODES];
__device__ int   g_src[N_EDGES];
__device__ float g_norm[N_EDGES];
__device__ float g_hw[N_NODES * D];   // GEMM output (h @ W)
__device__ float g_h [N_NODES * D];   // current layer features

// -------- CSR build --------
__global__ void init_deg_kernel() {
    int i = blockIdx.x * blockDim.x + threadIdx.x;
    if (i < N_NODES) g_deg[i] = 0;
}

__global__ void count_kernel(const int* __restrict__ col) {
    int e = blockIdx.x * blockDim.x + threadIdx.x;
    if (e < N_EDGES) atomicAdd(&g_deg[col[e]], 1);
}

__global__ void dinv_kernel() {
    int i = blockIdx.x * blockDim.x + threadIdx.x;
    if (i < N_NODES) g_dinv[i] = rsqrtf((float)(g_deg[i] + 1));  // +1 self loop
}

// single-block exclusive scan over g_deg -> g_off, g_cursor
__global__ void scan_kernel() {
    __shared__ int ssum[1024];
    const int tid = threadIdx.x;
    const int CH = (N_NODES + 1023) / 1024;  // 49
    int start = tid * CH;
    int end = min(start + CH, N_NODES);
    int s = 0;
    for (int i = start; i < end; i++) s += g_deg[i];
    ssum[tid] = s;
    __syncthreads();
    // Hillis-Steele inclusive scan
    for (int d = 1; d < 1024; d <<= 1) {
        int v = (tid >= d) ? ssum[tid - d] : 0;
        __syncthreads();
        ssum[tid] += v;
        __syncthreads();
    }
    int prefix = (tid == 0) ? 0 : ssum[tid - 1];
    for (int i = start; i < end; i++) {
        g_off[i] = prefix;
        g_cursor[i] = prefix;
        prefix += g_deg[i];
    }
    if (tid == 1023) g_off[N_NODES] = prefix;
}

__global__ void fill_kernel(const int* __restrict__ row, const int* __restrict__ col) {
    int e = blockIdx.x * blockDim.x + threadIdx.x;
    if (e < N_EDGES) {
        int r = row[e], c = col[e];
        int p = atomicAdd(&g_cursor[c], 1);
        g_src[p] = r;
        g_norm[p] = g_dinv[r] * g_dinv[c];
    }
}

// -------- GEMM: C[M,128] = A[M,128] @ W[128,128], fp32 --------
// Tile 128x128, K-chunk 32, 256 threads, 8x8 microtile per thread.
__global__ __launch_bounds__(256) void gemm_kernel(const float* __restrict__ A,
                                                   const float* __restrict__ W,
                                                   float* __restrict__ C) {
    __shared__ float As[32][128];
    __shared__ float Bs[32][128];
    const int tid = threadIdx.x;
    const int bm = blockIdx.x * 128;
    const int tx = tid & 15;        // 0..15 -> cols
    const int ty = tid >> 4;        // 0..15 -> rows
    float acc[8][8];
#pragma unroll
    for (int i = 0; i < 8; i++)
#pragma unroll
        for (int j = 0; j < 8; j++) acc[i][j] = 0.f;

    for (int k0 = 0; k0 < D; k0 += 32) {
        // load A tile: 128 rows x 32 cols (transposed into As[k][m])
#pragma unroll
        for (int i = 0; i < 4; i++) {
            int f = tid + i * 256;          // 0..1023
            int m = f >> 3;                 // 0..127
            int k4 = (f & 7) * 4;           // 0,4,...,28
            float4 v = make_float4(0.f, 0.f, 0.f, 0.f);
            int gm = bm + m;
            if (gm < N_NODES) v = *(const float4*)(A + (size_t)gm * D + k0 + k4);
            As[k4 + 0][m] = v.x;
            As[k4 + 1][m] = v.y;
            As[k4 + 2][m] = v.z;
            As[k4 + 3][m] = v.w;
        }
        // load B tile: rows k0..k0+31, all 128 cols
#pragma unroll
        for (int i = 0; i < 4; i++) {
            int f = tid + i * 256;
            int k = f >> 5;                 // 0..31
            int n4 = (f & 31) * 4;          // 0..124
            *(float4*)&Bs[k][n4] = *(const float4*)(W + (size_t)(k0 + k) * D + n4);
        }
        __syncthreads();
#pragma unroll
        for (int kk = 0; kk < 32; kk++) {
            float a[8], b[8];
            *(float4*)&a[0] = *(float4*)&As[kk][ty * 8];
            *(float4*)&a[4] = *(float4*)&As[kk][ty * 8 + 4];
            *(float4*)&b[0] = *(float4*)&Bs[kk][tx * 8];
            *(float4*)&b[4] = *(float4*)&Bs[kk][tx * 8 + 4];
#pragma unroll
            for (int i = 0; i < 8; i++)
#pragma unroll
                for (int j = 0; j < 8; j++) acc[i][j] += a[i] * b[j];
        }
        __syncthreads();
    }
#pragma unroll
    for (int i = 0; i < 8; i++) {
        int gm = bm + ty * 8 + i;
        if (gm < N_NODES) {
            float4 o0 = make_float4(acc[i][0], acc[i][1], acc[i][2], acc[i][3]);
            float4 o1 = make_float4(acc[i][4], acc[i][5], acc[i][6], acc[i][7]);
            *(float4*)(C + (size_t)gm * D + tx * 8)     = o0;
            *(float4*)(C + (size_t)gm * D + tx * 8 + 4) = o1;
        }
    }
}

// -------- Aggregation: warp per node, no atomics --------
__global__ __launch_bounds__(256) void agg_kernel(const float* __restrict__ hw,
                                                  const float* __restrict__ bias,
                                                  float* __restrict__ hout,
                                                  float* __restrict__ out,
                                                  int layer) {
    int warp = (blockIdx.x * blockDim.x + threadIdx.x) >> 5;
    int lane = threadIdx.x & 31;
    if (warp >= N_NODES) return;
    const int t = warp;
    const float4* __restrict__ hw4 = (const float4*)hw;

    float dv = g_dinv[t];
    float s = dv * dv;               // self-loop norm
    float4 v = hw4[(size_t)t * 32 + lane];
    float ax = s * v.x, ay = s * v.y, az = s * v.z, aw = s * v.w;

    int e0 = g_off[t], e1 = g_off[t + 1];
    for (int e = e0; e < e1; e++) {
        int src = g_src[e];
        float nrm = g_norm[e];
        float4 u = hw4[(size_t)src * 32 + lane];
        ax += nrm * u.x;
        ay += nrm * u.y;
        az += nrm * u.z;
        aw += nrm * u.w;
    }
    float4 bb = ((const float4*)bias)[lane];
    float4 r;
    r.x = tanhf(ax + bb.x);
    r.y = tanhf(ay + bb.y);
    r.z = tanhf(az + bb.z);
    r.w = tanhf(aw + bb.w);

    ((float4*)hout)[(size_t)t * 32 + lane] = r;
    ((float4*)out)[((size_t)t * 3 + layer) * 32 + lane] = r;
}

// -------- launch --------
extern "C" void kernel_launch(void* const* d_in, const int* in_sizes, int n_in,
                              void* d_out, int out_size) {
    const float* x   = (const float*)d_in[0];
    const int*   ei  = (const int*)d_in[1];
    const float* W0  = (const float*)d_in[2];
    const float* b0  = (const float*)d_in[3];
    const float* W1  = (const float*)d_in[4];
    const float* b1  = (const float*)d_in[5];
    const float* W2  = (const float*)d_in[6];
    const float* b2  = (const float*)d_in[7];
    float* out = (float*)d_out;

    const int* row = ei;             // edge_index[0]
    const int* col = ei + N_EDGES;   // edge_index[1]

    float* hw; cudaGetSymbolAddress((void**)&hw, g_hw);
    float* h;  cudaGetSymbolAddress((void**)&h,  g_h);

    const int TB = 256;
    init_deg_kernel<<<(N_NODES + TB - 1) / TB, TB>>>();
    count_kernel<<<(N_EDGES + TB - 1) / TB, TB>>>(col);
    dinv_kernel<<<(N_NODES + TB - 1) / TB, TB>>>();
    scan_kernel<<<1, 1024>>>();
    fill_kernel<<<(N_EDGES + TB - 1) / TB, TB>>>(row, col);

    const int gemm_grid = (N_NODES + 127) / 128;       // 391
    const int agg_grid  = (N_NODES * 32 + TB - 1) / TB; // 6250

    const float* Ws[3] = {W0, W1, W2};
    const float* bs[3] = {b0, b1, b2};
    const float* in = x;
    for (int l = 0; l < 3; l++) {
        gemm_kernel<<<gemm_grid, 256>>>(in, Ws[l], hw);
        agg_kernel<<<agg_grid, 256>>>(hw, bs[l], h, out, l);
        in = h;
    }
}

// round 3
// speedup vs baseline: 1.1789x; 1.1789x over previous
#include <cuda_runtime.h>
#include <cuda_bf16.h>
#include <math.h>

#define N_NODES 50000
#define N_EDGES 800000
#define D 128
#define NBS 196            // ceil(50000/256) scan blocks

// -------- scratch (no allocations allowed) --------
__device__ int   g_deg[N_NODES];
__device__ float g_dinv[N_NODES];
__device__ int   g_off[N_NODES + 1];
__device__ int   g_cursor[N_NODES];
__device__ int   g_src[N_EDGES];
__device__ float g_norm[N_EDGES];
__device__ int   g_bsum[256];
__device__ int   g_boff[256];
__device__ float g_hw[N_NODES * D];   // GEMM output (h @ W)
__device__ float g_h [N_NODES * D];   // current layer features

// -------- packed f32x2 helpers --------
__device__ __forceinline__ unsigned long long pack2(float x, float y) {
    unsigned long long r;
    asm("mov.b64 %0, {%1, %2};" : "=l"(r) : "f"(x), "f"(y));
    return r;
}
__device__ __forceinline__ void ffma2(unsigned long long& d,
                                      unsigned long long a,
                                      unsigned long long b) {
    asm("fma.rn.f32x2 %0, %1, %2, %0;" : "+l"(d) : "l"(a), "l"(b));
}
union U64F2 { unsigned long long u; float2 f; };

// -------- CSR build --------
__global__ void init_deg_kernel() {
    int i = blockIdx.x * blockDim.x + threadIdx.x;
    if (i < N_NODES) g_deg[i] = 0;
}

__global__ void count_kernel(const int* __restrict__ col) {
    int e = blockIdx.x * blockDim.x + threadIdx.x;
    if (e < N_EDGES) atomicAdd(&g_deg[col[e]], 1);
}

// pass1: dinv + per-block degree sums (256 nodes per block)
__global__ __launch_bounds__(256) void scan_pass1() {
    __shared__ int s[256];
    int t = threadIdx.x;
    int i = blockIdx.x * 256 + t;
    int d = (i < N_NODES) ? g_deg[i] : 0;
    if (i < N_NODES) g_dinv[i] = rsqrtf((float)(d + 1));  // +1 self loop
    s[t] = d;
    __syncthreads();
#pragma unroll
    for (int o = 128; o > 0; o >>= 1) {
        if (t < o) s[t] += s[t + o];
        __syncthreads();
    }
    if (t == 0) g_bsum[blockIdx.x] = s[0];
}

// pass2: single-block exclusive scan of 196 block sums
__global__ __launch_bounds__(256) void scan_pass2() {
    __shared__ int s[256];
    int t = threadIdx.x;
    int v = (t < NBS) ? g_bsum[t] : 0;
    s[t] = v;
    __syncthreads();
#pragma unroll
    for (int dd = 1; dd < 256; dd <<= 1) {
        int u = (t >= dd) ? s[t - dd] : 0;
        __syncthreads();
        s[t] += u;
        __syncthreads();
    }
    if (t < NBS) g_boff[t] = s[t] - v;   // exclusive
    if (t == 255) g_off[N_NODES] = s[255];
}

// pass3: per-block exclusive scan + global offset -> g_off, g_cursor
__global__ __launch_bounds__(256) void scan_pass3() {
    __shared__ int s[256];
    int t = threadIdx.x;
    int i = blockIdx.x * 256 + t;
    int d = (i < N_NODES) ? g_deg[i] : 0;
    s[t] = d;
    __syncthreads();
#pragma unroll
    for (int o = 1; o < 256; o <<= 1) {
        int u = (t >= o) ? s[t - o] : 0;
        __syncthreads();
        s[t] += u;
        __syncthreads();
    }
    int excl = s[t] - d + g_boff[blockIdx.x];
    if (i < N_NODES) {
        g_off[i] = excl;
        g_cursor[i] = excl;
    }
}

__global__ void fill_kernel(const int* __restrict__ row, const int* __restrict__ col) {
    int e = blockIdx.x * blockDim.x + threadIdx.x;
    if (e < N_EDGES) {
        int r = row[e], c = col[e];
        int p = atomicAdd(&g_cursor[c], 1);
        g_src[p] = r;
        g_norm[p] = g_dinv[r] * g_dinv[c];
    }
}

// -------- GEMM: C[M,128] = A[M,128] @ W[128,128], fp32, FFMA2 inner --------
// Tile 128x128, K-chunk 32, 256 threads, 8x8 microtile per thread (as 8x4 f32x2).
__global__ __launch_bounds__(256) void gemm_kernel(const float* __restrict__ A,
                                                   const float* __restrict__ W,
                                                   float* __restrict__ C) {
    __shared__ float As[32][128];
    __shared__ float Bs[32][128];
    const int tid = threadIdx.x;
    const int bm = blockIdx.x * 128;
    const int tx = tid & 15;        // 0..15 -> col octet
    const int ty = tid >> 4;        // 0..15 -> row octet
    unsigned long long acc2[8][4];
#pragma unroll
    for (int i = 0; i < 8; i++)
#pragma unroll
        for (int j = 0; j < 4; j++) acc2[i][j] = 0ull;

    for (int k0 = 0; k0 < D; k0 += 32) {
        // load A tile: 128 rows x 32 cols (transposed into As[k][m])
#pragma unroll
        for (int i = 0; i < 4; i++) {
            int f = tid + i * 256;          // 0..1023
            int m = f >> 3;                 // 0..127
            int k4 = (f & 7) * 4;           // 0,4,...,28
            float4 v = make_float4(0.f, 0.f, 0.f, 0.f);
            int gm = bm + m;
            if (gm < N_NODES) v = *(const float4*)(A + (size_t)gm * D + k0 + k4);
            As[k4 + 0][m] = v.x;
            As[k4 + 1][m] = v.y;
            As[k4 + 2][m] = v.z;
            As[k4 + 3][m] = v.w;
        }
        // load B tile: rows k0..k0+31, all 128 cols
#pragma unroll
        for (int i = 0; i < 4; i++) {
            int f = tid + i * 256;
            int k = f >> 5;                 // 0..31
            int n4 = (f & 31) * 4;          // 0..124
            *(float4*)&Bs[k][n4] = *(const float4*)(W + (size_t)(k0 + k) * D + n4);
        }
        __syncthreads();
#pragma unroll
        for (int kk = 0; kk < 32; kk++) {
            float a[8];
            *(float4*)&a[0] = *(float4*)&As[kk][ty * 8];
            *(float4*)&a[4] = *(float4*)&As[kk][ty * 8 + 4];
            unsigned long long b2[4];
            const unsigned long long* brow =
                (const unsigned long long*)&Bs[kk][tx * 8];
            b2[0] = brow[0]; b2[1] = brow[1]; b2[2] = brow[2]; b2[3] = brow[3];
#pragma unroll
            for (int i = 0; i < 8; i++) {
                unsigned long long a2 = pack2(a[i], a[i]);
#pragma unroll
                for (int j = 0; j < 4; j++) ffma2(acc2[i][j], a2, b2[j]);
            }
        }
        __syncthreads();
    }
#pragma unroll
    for (int i = 0; i < 8; i++) {
        int gm = bm + ty * 8 + i;
        if (gm < N_NODES) {
            U64F2 u0, u1, u2, u3;
            u0.u = acc2[i][0]; u1.u = acc2[i][1];
            u2.u = acc2[i][2]; u3.u = acc2[i][3];
            float4 o0 = make_float4(u0.f.x, u0.f.y, u1.f.x, u1.f.y);
            float4 o1 = make_float4(u2.f.x, u2.f.y, u3.f.x, u3.f.y);
            *(float4*)(C + (size_t)gm * D + tx * 8)     = o0;
            *(float4*)(C + (size_t)gm * D + tx * 8 + 4) = o1;
        }
    }
}

// -------- Aggregation: warp per node, no atomics --------
__global__ __launch_bounds__(256) void agg_kernel(const float* __restrict__ hw,
                                                  const float* __restrict__ bias,
                                                  float* __restrict__ hout,
                                                  float* __restrict__ out,
                                                  int layer) {
    int warp = (blockIdx.x * blockDim.x + threadIdx.x) >> 5;
    int lane = threadIdx.x & 31;
    if (warp >= N_NODES) return;
    const int t = warp;
    const float4* __restrict__ hw4 = (const float4*)hw;

    float dv = g_dinv[t];
    float s = dv * dv;               // self-loop norm
    float4 v = hw4[(size_t)t * 32 + lane];
    float ax = s * v.x, ay = s * v.y, az = s * v.z, aw = s * v.w;

    int e0 = g_off[t], e1 = g_off[t + 1];
#pragma unroll 4
    for (int e = e0; e < e1; e++) {
        int src = g_src[e];
        float nrm = g_norm[e];
        float4 u = hw4[(size_t)src * 32 + lane];
        ax += nrm * u.x;
        ay += nrm * u.y;
        az += nrm * u.z;
        aw += nrm * u.w;
    }
    float4 bb = ((const float4*)bias)[lane];
    float4 r;
    r.x = tanhf(ax + bb.x);
    r.y = tanhf(ay + bb.y);
    r.z = tanhf(az + bb.z);
    r.w = tanhf(aw + bb.w);

    ((float4*)hout)[(size_t)t * 32 + lane] = r;
    ((float4*)out)[((size_t)t * 3 + layer) * 32 + lane] = r;
}

// -------- launch --------
extern "C" void kernel_launch(void* const* d_in, const int* in_sizes, int n_in,
                              void* d_out, int out_size) {
    const float* x   = (const float*)d_in[0];
    const int*   ei  = (const int*)d_in[1];
    const float* W0  = (const float*)d_in[2];
    const float* b0  = (const float*)d_in[3];
    const float* W1  = (const float*)d_in[4];
    const float* b1  = (const float*)d_in[5];
    const float* W2  = (const float*)d_in[6];
    const float* b2  = (const float*)d_in[7];
    float* out = (float*)d_out;

    const int* row = ei;             // edge_index[0]
    const int* col = ei + N_EDGES;   // edge_index[1]

    float* hw; cudaGetSymbolAddress((void**)&hw, g_hw);
    float* h;  cudaGetSymbolAddress((void**)&h,  g_h);

    const int TB = 256;
    init_deg_kernel<<<(N_NODES + TB - 1) / TB, TB>>>();
    count_kernel<<<(N_EDGES + TB - 1) / TB, TB>>>(col);
    scan_pass1<<<NBS, 256>>>();
    scan_pass2<<<1, 256>>>();
    scan_pass3<<<NBS, 256>>>();
    fill_kernel<<<(N_EDGES + TB - 1) / TB, TB>>>(row, col);

    const int gemm_grid = (N_NODES + 127) / 128;        // 391
    const int agg_grid  = (N_NODES * 32 + TB - 1) / TB; // 6250

    const float* Ws[3] = {W0, W1, W2};
    const float* bs[3] = {b0, b1, b2};
    const float* in = x;
    for (int l = 0; l < 3; l++) {
        gemm_kernel<<<gemm_grid, 256>>>(in, Ws[l], hw);
        agg_kernel<<<agg_grid, 256>>>(hw, bs[l], h, out, l);
        in = h;
    }
}

// round 4
// speedup vs baseline: 1.4265x; 1.2101x over previous
#include <cuda_runtime.h>
#include <cuda_fp16.h>
#include <math.h>

#define N_NODES 50000
#define N_EDGES 800000
#define D 128
#define NBS 196            // ceil(50000/256) scan blocks

// -------- scratch (no allocations allowed) --------
__device__ int    g_deg[N_NODES];
__device__ float  g_dinv[N_NODES];
__device__ int    g_off[N_NODES + 1];
__device__ int    g_cursor[N_NODES];
__device__ int    g_src[N_EDGES];
__device__ int    g_bsum[256];
__device__ int    g_boff[256];
__device__ __half g_hws[N_NODES * D];  // fp16: dinv[row] * (h @ W)
__device__ float  g_h  [N_NODES * D];  // current layer features (fp32)

// -------- packed f32x2 helpers --------
__device__ __forceinline__ unsigned long long pack2(float x, float y) {
    unsigned long long r;
    asm("mov.b64 %0, {%1, %2};" : "=l"(r) : "f"(x), "f"(y));
    return r;
}
__device__ __forceinline__ void ffma2(unsigned long long& d,
                                      unsigned long long a,
                                      unsigned long long b) {
    asm("fma.rn.f32x2 %0, %1, %2, %0;" : "+l"(d) : "l"(a), "l"(b));
}
union U64F2 { unsigned long long u; float2 f; };

// -------- CSR build --------
__global__ void init_deg_kernel() {
    int i = blockIdx.x * blockDim.x + threadIdx.x;
    if (i < N_NODES) g_deg[i] = 0;
}

__global__ void count_kernel(const int* __restrict__ col) {
    int e = blockIdx.x * blockDim.x + threadIdx.x;
    if (e < N_EDGES) atomicAdd(&g_deg[col[e]], 1);
}

// pass1: dinv + per-block degree sums (256 nodes per block)
__global__ __launch_bounds__(256) void scan_pass1() {
    __shared__ int s[256];
    int t = threadIdx.x;
    int i = blockIdx.x * 256 + t;
    int d = (i < N_NODES) ? g_deg[i] : 0;
    if (i < N_NODES) g_dinv[i] = rsqrtf((float)(d + 1));  // +1 self loop
    s[t] = d;
    __syncthreads();
#pragma unroll
    for (int o = 128; o > 0; o >>= 1) {
        if (t < o) s[t] += s[t + o];
        __syncthreads();
    }
    if (t == 0) g_bsum[blockIdx.x] = s[0];
}

// pass2: single-block exclusive scan of 196 block sums
__global__ __launch_bounds__(256) void scan_pass2() {
    __shared__ int s[256];
    int t = threadIdx.x;
    int v = (t < NBS) ? g_bsum[t] : 0;
    s[t] = v;
    __syncthreads();
#pragma unroll
    for (int dd = 1; dd < 256; dd <<= 1) {
        int u = (t >= dd) ? s[t - dd] : 0;
        __syncthreads();
        s[t] += u;
        __syncthreads();
    }
    if (t < NBS) g_boff[t] = s[t] - v;   // exclusive
    if (t == 255) g_off[N_NODES] = s[255];
}

// pass3: per-block exclusive scan + global offset -> g_off, g_cursor
__global__ __launch_bounds__(256) void scan_pass3() {
    __shared__ int s[256];
    int t = threadIdx.x;
    int i = blockIdx.x * 256 + t;
    int d = (i < N_NODES) ? g_deg[i] : 0;
    s[t] = d;
    __syncthreads();
#pragma unroll
    for (int o = 1; o < 256; o <<= 1) {
        int u = (t >= o) ? s[t - o] : 0;
        __syncthreads();
        s[t] += u;
        __syncthreads();
    }
    int excl = s[t] - d + g_boff[blockIdx.x];
    if (i < N_NODES) {
        g_off[i] = excl;
        g_cursor[i] = excl;
    }
}

__global__ void fill_kernel(const int* __restrict__ row, const int* __restrict__ col) {
    int e = blockIdx.x * blockDim.x + threadIdx.x;
    if (e < N_EDGES) {
        int r = row[e], c = col[e];
        int p = atomicAdd(&g_cursor[c], 1);
        g_src[p] = r;
    }
}

// -------- GEMM: hws[M,128] = fp16( dinv[m] * (A[M,128] @ W[128,128]) ) --------
// Tile 128x128, K-chunk 32, 256 threads, 8x8 microtile per thread (as 8x4 f32x2).
__global__ __launch_bounds__(256) void gemm_kernel(const float* __restrict__ A,
                                                   const float* __restrict__ W,
                                                   __half* __restrict__ C) {
    __shared__ float As[32][128];
    __shared__ float Bs[32][128];
    const int tid = threadIdx.x;
    const int bm = blockIdx.x * 128;
    const int tx = tid & 15;        // 0..15 -> col octet
    const int ty = tid >> 4;        // 0..15 -> row octet
    unsigned long long acc2[8][4];
#pragma unroll
    for (int i = 0; i < 8; i++)
#pragma unroll
        for (int j = 0; j < 4; j++) acc2[i][j] = 0ull;

    for (int k0 = 0; k0 < D; k0 += 32) {
#pragma unroll
        for (int i = 0; i < 4; i++) {
            int f = tid + i * 256;          // 0..1023
            int m = f >> 3;                 // 0..127
            int k4 = (f & 7) * 4;           // 0,4,...,28
            float4 v = make_float4(0.f, 0.f, 0.f, 0.f);
            int gm = bm + m;
            if (gm < N_NODES) v = *(const float4*)(A + (size_t)gm * D + k0 + k4);
            As[k4 + 0][m] = v.x;
            As[k4 + 1][m] = v.y;
            As[k4 + 2][m] = v.z;
            As[k4 + 3][m] = v.w;
        }
#pragma unroll
        for (int i = 0; i < 4; i++) {
            int f = tid + i * 256;
            int k = f >> 5;                 // 0..31
            int n4 = (f & 31) * 4;          // 0..124
            *(float4*)&Bs[k][n4] = *(const float4*)(W + (size_t)(k0 + k) * D + n4);
        }
        __syncthreads();
#pragma unroll
        for (int kk = 0; kk < 32; kk++) {
            float a[8];
            *(float4*)&a[0] = *(float4*)&As[kk][ty * 8];
            *(float4*)&a[4] = *(float4*)&As[kk][ty * 8 + 4];
            unsigned long long b2[4];
            const unsigned long long* brow =
                (const unsigned long long*)&Bs[kk][tx * 8];
            b2[0] = brow[0]; b2[1] = brow[1]; b2[2] = brow[2]; b2[3] = brow[3];
#pragma unroll
            for (int i = 0; i < 8; i++) {
                unsigned long long a2 = pack2(a[i], a[i]);
#pragma unroll
                for (int j = 0; j < 4; j++) ffma2(acc2[i][j], a2, b2[j]);
            }
        }
        __syncthreads();
    }
#pragma unroll
    for (int i = 0; i < 8; i++) {
        int gm = bm + ty * 8 + i;
        if (gm < N_NODES) {
            float dv = g_dinv[gm];
            U64F2 u0, u1, u2, u3;
            u0.u = acc2[i][0]; u1.u = acc2[i][1];
            u2.u = acc2[i][2]; u3.u = acc2[i][3];
            __half2 p[4];
            p[0] = __float22half2_rn(make_float2(u0.f.x * dv, u0.f.y * dv));
            p[1] = __float22half2_rn(make_float2(u1.f.x * dv, u1.f.y * dv));
            p[2] = __float22half2_rn(make_float2(u2.f.x * dv, u2.f.y * dv));
            p[3] = __float22half2_rn(make_float2(u3.f.x * dv, u3.f.y * dv));
            *(uint4*)(C + (size_t)gm * D + tx * 8) = *(uint4*)p;
        }
    }
}

// -------- Aggregation: warp per node, fp16 gather, no per-edge norm --------
// agg[t] = dinv[t] * ( hws[t] + sum_e hws[src_e] );  h = tanh(agg + b)
__global__ __launch_bounds__(256) void agg_kernel(const __half* __restrict__ hws,
                                                  const float* __restrict__ bias,
                                                  float* __restrict__ hout,
                                                  float* __restrict__ out,
                                                  int layer) {
    int warp = (blockIdx.x * blockDim.x + threadIdx.x) >> 5;
    int lane = threadIdx.x & 31;
    if (warp >= N_NODES) return;
    const int t = warp;

    float s0, s1, s2, s3;
    {   // self-loop term: hws[t] (already scaled by dinv[t])
        uint2 u = *(const uint2*)(hws + (size_t)t * D + lane * 4);
        __half2 h0 = *reinterpret_cast<__half2*>(&u.x);
        __half2 h1 = *reinterpret_cast<__half2*>(&u.y);
        float2 f0 = __half22float2(h0), f1 = __half22float2(h1);
        s0 = f0.x; s1 = f0.y; s2 = f1.x; s3 = f1.y;
    }

    int e0 = g_off[t], e1 = g_off[t + 1];
#pragma unroll 4
    for (int e = e0; e < e1; e++) {
        int src = g_src[e];
        uint2 u = *(const uint2*)(hws + (size_t)src * D + lane * 4);
        __half2 h0 = *reinterpret_cast<__half2*>(&u.x);
        __half2 h1 = *reinterpret_cast<__half2*>(&u.y);
        float2 f0 = __half22float2(h0), f1 = __half22float2(h1);
        s0 += f0.x; s1 += f0.y; s2 += f1.x; s3 += f1.y;
    }

    float dv = g_dinv[t];
    float4 bb = ((const float4*)bias)[lane];
    float4 r;
    r.x = tanhf(fmaf(dv, s0, bb.x));
    r.y = tanhf(fmaf(dv, s1, bb.y));
    r.z = tanhf(fmaf(dv, s2, bb.z));
    r.w = tanhf(fmaf(dv, s3, bb.w));

    ((float4*)hout)[(size_t)t * 32 + lane] = r;
    ((float4*)out)[((size_t)t * 3 + layer) * 32 + lane] = r;
}

// -------- launch --------
extern "C" void kernel_launch(void* const* d_in, const int* in_sizes, int n_in,
                              void* d_out, int out_size) {
    const float* x   = (const float*)d_in[0];
    const int*   ei  = (const int*)d_in[1];
    const float* W0  = (const float*)d_in[2];
    const float* b0  = (const float*)d_in[3];
    const float* W1  = (const float*)d_in[4];
    const float* b1  = (const float*)d_in[5];
    const float* W2  = (const float*)d_in[6];
    const float* b2  = (const float*)d_in[7];
    float* out = (float*)d_out;

    const int* row = ei;             // edge_index[0]
    const int* col = ei + N_EDGES;   // edge_index[1]

    __half* hws; cudaGetSymbolAddress((void**)&hws, g_hws);
    float*  h;   cudaGetSymbolAddress((void**)&h,  g_h);

    const int TB = 256;
    init_deg_kernel<<<(N_NODES + TB - 1) / TB, TB>>>();
    count_kernel<<<(N_EDGES + TB - 1) / TB, TB>>>(col);
    scan_pass1<<<NBS, 256>>>();
    scan_pass2<<<1, 256>>>();
    scan_pass3<<<NBS, 256>>>();
    fill_kernel<<<(N_EDGES + TB - 1) / TB, TB>>>(row, col);

    const int gemm_grid = (N_NODES + 127) / 128;        // 391
    const int agg_grid  = (N_NODES * 32 + TB - 1) / TB; // 6250

    const float* Ws[3] = {W0, W1, W2};
    const float* bs[3] = {b0, b1, b2};
    const float* in = x;
    for (int l = 0; l < 3; l++) {
        gemm_kernel<<<gemm_grid, 256>>>(in, Ws[l], hws);
        agg_kernel<<<agg_grid, 256>>>(hws, bs[l], h, out, l);
        in = h;
    }
}

// round 5
// speedup vs baseline: 1.5681x; 1.0992x over previous
#include <cuda_runtime.h>
#include <cuda_fp16.h>
#include <mma.h>
#include <math.h>

using namespace nvcuda;

#define N_NODES 50000
#define N_EDGES 800000
#define D 128
#define NBS 196            // ceil(50000/256) scan blocks

// -------- scratch (no allocations allowed) --------
__device__ int    g_deg[N_NODES];
__device__ float  g_dinv[N_NODES];
__device__ int    g_off[N_NODES + 1];
__device__ int    g_cursor[N_NODES];
__device__ int    g_src[N_EDGES];
__device__ int    g_bsum[256];
__device__ int    g_boff[256];
__device__ __half g_hws[N_NODES * D];   // fp16: dinv[row] * (h @ W)
__device__ __half g_hh [N_NODES * D];   // fp16 layer features (x16, then tanh outputs)
__device__ __half g_Wh [3 * D * D];     // fp16 weights

// -------- CSR build --------
__global__ void init_deg_kernel() {
    int i = blockIdx.x * blockDim.x + threadIdx.x;
    if (i < N_NODES) g_deg[i] = 0;
}

__global__ void count_kernel(const int* __restrict__ col) {
    int e = blockIdx.x * blockDim.x + threadIdx.x;
    if (e < N_EDGES) atomicAdd(&g_deg[col[e]], 1);
}

// pass1: dinv + per-block degree sums (256 nodes per block)
__global__ __launch_bounds__(256) void scan_pass1() {
    __shared__ int s[256];
    int t = threadIdx.x;
    int i = blockIdx.x * 256 + t;
    int d = (i < N_NODES) ? g_deg[i] : 0;
    if (i < N_NODES) g_dinv[i] = rsqrtf((float)(d + 1));  // +1 self loop
    s[t] = d;
    __syncthreads();
#pragma unroll
    for (int o = 128; o > 0; o >>= 1) {
        if (t < o) s[t] += s[t + o];
        __syncthreads();
    }
    if (t == 0) g_bsum[blockIdx.x] = s[0];
}

// pass2: single-block exclusive scan of 196 block sums
__global__ __launch_bounds__(256) void scan_pass2() {
    __shared__ int s[256];
    int t = threadIdx.x;
    int v = (t < NBS) ? g_bsum[t] : 0;
    s[t] = v;
    __syncthreads();
#pragma unroll
    for (int dd = 1; dd < 256; dd <<= 1) {
        int u = (t >= dd) ? s[t - dd] : 0;
        __syncthreads();
        s[t] += u;
        __syncthreads();
    }
    if (t < NBS) g_boff[t] = s[t] - v;   // exclusive
    if (t == 255) g_off[N_NODES] = s[255];
}

// pass3: per-block exclusive scan + global offset -> g_off, g_cursor
__global__ __launch_bounds__(256) void scan_pass3() {
    __shared__ int s[256];
    int t = threadIdx.x;
    int i = blockIdx.x * 256 + t;
    int d = (i < N_NODES) ? g_deg[i] : 0;
    s[t] = d;
    __syncthreads();
#pragma unroll
    for (int o = 1; o < 256; o <<= 1) {
        int u = (t >= o) ? s[t - o] : 0;
        __syncthreads();
        s[t] += u;
        __syncthreads();
    }
    int excl = s[t] - d + g_boff[blockIdx.x];
    if (i < N_NODES) {
        g_off[i] = excl;
        g_cursor[i] = excl;
    }
}

__global__ void fill_kernel(const int* __restrict__ row, const int* __restrict__ col) {
    int e = blockIdx.x * blockDim.x + threadIdx.x;
    if (e < N_EDGES) {
        int r = row[e], c = col[e];
        int p = atomicAdd(&g_cursor[c], 1);
        g_src[p] = r;
    }
}

// -------- fp32 -> fp16 converters --------
__global__ __launch_bounds__(256) void convert_x_kernel(const float* __restrict__ x) {
    // 8 elements per thread
    size_t i = ((size_t)blockIdx.x * blockDim.x + threadIdx.x) * 8;
    if (i >= (size_t)N_NODES * D) return;
    float4 a = *(const float4*)(x + i);
    float4 b = *(const float4*)(x + i + 4);
    __half2 o[4];
    o[0] = __float22half2_rn(make_float2(a.x, a.y));
    o[1] = __float22half2_rn(make_float2(a.z, a.w));
    o[2] = __float22half2_rn(make_float2(b.x, b.y));
    o[3] = __float22half2_rn(make_float2(b.z, b.w));
    *(uint4*)(g_hh + i) = *(uint4*)o;
}

__global__ __launch_bounds__(256) void convert_w_kernel(const float* __restrict__ W0,
                                                        const float* __restrict__ W1,
                                                        const float* __restrict__ W2) {
    int i = (blockIdx.x * blockDim.x + threadIdx.x) * 8;   // within one W
    if (i >= D * D) return;
    const float* Ws[3] = {W0, W1, W2};
#pragma unroll
    for (int l = 0; l < 3; l++) {
        float4 a = *(const float4*)(Ws[l] + i);
        float4 b = *(const float4*)(Ws[l] + i + 4);
        __half2 o[4];
        o[0] = __float22half2_rn(make_float2(a.x, a.y));
        o[1] = __float22half2_rn(make_float2(a.z, a.w));
        o[2] = __float22half2_rn(make_float2(b.x, b.y));
        o[3] = __float22half2_rn(make_float2(b.z, b.w));
        *(uint4*)(g_Wh + l * D * D + i) = *(uint4*)o;
    }
}

// -------- GEMM: hws = fp16( dinv[m] * (A[M,128] @ W[128,128]) ), HMMA --------
// Block: 128 rows x 128 cols, 256 threads (8 warps), warp = 16 rows x 128 cols.
// smem: phase 1 = A tile (128x128 fp16, 32KB) + W (128x128 fp16, 32KB)
//       phase 2 = reuse as 128x128 fp32 staging (64KB)
__global__ __launch_bounds__(256) void gemm_hmma(const __half* __restrict__ A,
                                                 const __half* __restrict__ Wh,
                                                 __half* __restrict__ C) {
    extern __shared__ char smem[];
    __half* As = (__half*)smem;          // [128][128]
    __half* Bs = As + D * D;             // [128][128]
    const int tid  = threadIdx.x;
    const int warp = tid >> 5;
    const int lane = tid & 31;
    const int bm = blockIdx.x * 128;

    // load A tile (zero-pad OOB rows) and W; 2048 uint4 each, 256 threads
    {
        const uint4* Ag = (const uint4*)(A + (size_t)bm * D);
        uint4* As4 = (uint4*)As;
        const uint4* Wg = (const uint4*)Wh;
        uint4* Bs4 = (uint4*)Bs;
#pragma unroll
        for (int it = 0; it < 8; it++) {
            int i = tid + it * 256;          // 0..2047
            int r = i >> 4;                  // row (16 uint4 per row)
            uint4 v = make_uint4(0u, 0u, 0u, 0u);
            if (bm + r < N_NODES) v = Ag[i];
            As4[i] = v;
            Bs4[i] = Wg[i];
        }
    }
    __syncthreads();

    wmma::fragment<wmma::accumulator, 16, 16, 16, float> acc[8];
#pragma unroll
    for (int j = 0; j < 8; j++) wmma::fill_fragment(acc[j], 0.0f);

    const __half* Abase = As + warp * 16 * D;
#pragma unroll
    for (int k = 0; k < D; k += 16) {
        wmma::fragment<wmma::matrix_a, 16, 16, 16, __half, wmma::row_major> af;
        wmma::load_matrix_sync(af, Abase + k, D);
#pragma unroll
        for (int j = 0; j < 8; j++) {
            wmma::fragment<wmma::matrix_b, 16, 16, 16, __half, wmma::row_major> bf;
            wmma::load_matrix_sync(bf, Bs + k * D + j * 16, D);
            wmma::mma_sync(acc[j], af, bf, acc[j]);
        }
    }
    __syncthreads();   // done reading As/Bs; reuse smem as fp32 staging

    float* Cs = (float*)smem + warp * 16 * D;   // this warp's 16x128 region
#pragma unroll
    for (int j = 0; j < 8; j++)
        wmma::store_matrix_sync(Cs + j * 16, acc[j], D, wmma::mem_row_major);
    __syncwarp();

    // scale by dinv[row], convert to fp16, store
#pragma unroll
    for (int it = 0; it < 8; it++) {
        int i = lane + it * 32;          // 0..255: 16 rows x 16 chunks of 8
        int r  = i >> 4;
        int c8 = (i & 15) * 8;
        int gm = bm + warp * 16 + r;
        if (gm < N_NODES) {
            float dv = g_dinv[gm];
            const float* p = Cs + r * D + c8;
            __half2 o[4];
#pragma unroll
            for (int q = 0; q < 4; q++)
                o[q] = __float22half2_rn(make_float2(p[2 * q] * dv, p[2 * q + 1] * dv));
            *(uint4*)(C + (size_t)gm * D + c8) = *(uint4*)o;
        }
    }
}

// -------- Aggregation: warp per node, fp16 gather, no per-edge norm --------
// agg[t] = dinv[t] * ( hws[t] + sum_e hws[src_e] );  h = tanh(agg + b)
__global__ __launch_bounds__(256) void agg_kernel(const __half* __restrict__ hws,
                                                  const float* __restrict__ bias,
                                                  __half* __restrict__ hout,
                                                  float* __restrict__ out,
                                                  int layer) {
    int warp = (blockIdx.x * blockDim.x + threadIdx.x) >> 5;
    int lane = threadIdx.x & 31;
    if (warp >= N_NODES) return;
    const int t = warp;

    float s0, s1, s2, s3;
    {   // self-loop term: hws[t] (already scaled by dinv[t])
        uint2 u = *(const uint2*)(hws + (size_t)t * D + lane * 4);
        __half2 h0 = *reinterpret_cast<__half2*>(&u.x);
        __half2 h1 = *reinterpret_cast<__half2*>(&u.y);
        float2 f0 = __half22float2(h0), f1 = __half22float2(h1);
        s0 = f0.x; s1 = f0.y; s2 = f1.x; s3 = f1.y;
    }

    int e0 = g_off[t], e1 = g_off[t + 1];
#pragma unroll 4
    for (int e = e0; e < e1; e++) {
        int src = g_src[e];
        uint2 u = *(const uint2*)(hws + (size_t)src * D + lane * 4);
        __half2 h0 = *reinterpret_cast<__half2*>(&u.x);
        __half2 h1 = *reinterpret_cast<__half2*>(&u.y);
        float2 f0 = __half22float2(h0), f1 = __half22float2(h1);
        s0 += f0.x; s1 += f0.y; s2 += f1.x; s3 += f1.y;
    }

    float dv = g_dinv[t];
    float4 bb = ((const float4*)bias)[lane];
    float r0 = tanhf(fmaf(dv, s0, bb.x));
    float r1 = tanhf(fmaf(dv, s1, bb.y));
    float r2 = tanhf(fmaf(dv, s2, bb.z));
    float r3 = tanhf(fmaf(dv, s3, bb.w));

    // fp16 copy for next layer's GEMM input
    __half2 o[2];
    o[0] = __float22half2_rn(make_float2(r0, r1));
    o[1] = __float22half2_rn(make_float2(r2, r3));
    *(uint2*)(hout + (size_t)t * D + lane * 4) = *(uint2*)o;

    // fp32 output
    float4 r = make_float4(r0, r1, r2, r3);
    ((float4*)out)[((size_t)t * 3 + layer) * 32 + lane] = r;
}

// -------- launch --------
extern "C" void kernel_launch(void* const* d_in, const int* in_sizes, int n_in,
                              void* d_out, int out_size) {
    const float* x   = (const float*)d_in[0];
    const int*   ei  = (const int*)d_in[1];
    const float* W0  = (const float*)d_in[2];
    const float* b0  = (const float*)d_in[3];
    const float* W1  = (const float*)d_in[4];
    const float* b1  = (const float*)d_in[5];
    const float* W2  = (const float*)d_in[6];
    const float* b2  = (const float*)d_in[7];
    float* out = (float*)d_out;

    const int* row = ei;             // edge_index[0]
    const int* col = ei + N_EDGES;   // edge_index[1]

    __half* hws; cudaGetSymbolAddress((void**)&hws, g_hws);
    __half* hh;  cudaGetSymbolAddress((void**)&hh,  g_hh);
    __half* wh;  cudaGetSymbolAddress((void**)&wh,  g_Wh);

    static bool attr_set = false;
    if (!attr_set) {
        cudaFuncSetAttribute(gemm_hmma,
                             cudaFuncAttributeMaxDynamicSharedMemorySize, 65536);
        attr_set = true;
    }

    const int TB = 256;
    init_deg_kernel<<<(N_NODES + TB - 1) / TB, TB>>>();
    count_kernel<<<(N_EDGES + TB - 1) / TB, TB>>>(col);
    scan_pass1<<<NBS, 256>>>();
    scan_pass2<<<1, 256>>>();
    scan_pass3<<<NBS, 256>>>();
    fill_kernel<<<(N_EDGES + TB - 1) / TB, TB>>>(row, col);

    convert_x_kernel<<<(N_NODES * D / 8 + TB - 1) / TB, TB>>>(x);
    convert_w_kernel<<<(D * D / 8 + TB - 1) / TB, TB>>>(W0, W1, W2);

    const int gemm_grid = (N_NODES + 127) / 128;        // 391
    const int agg_grid  = (N_NODES * 32 + TB - 1) / TB; // 6250

    const float* bs[3] = {b0, b1, b2};
    for (int l = 0; l < 3; l++) {
        gemm_hmma<<<gemm_grid, 256, 65536>>>(hh, wh + l * D * D, hws);
        agg_kernel<<<agg_grid, 256>>>(hws, bs[l], hh, out, l);
    }
}